// round 17
// baseline (speedup 1.0000x reference)
#include <cuda_runtime.h>
#include <cuda_bf16.h>
#include <cstdint>
#include <cstddef>

// Problem constants (fixed-shape problem)
#define BATCH 2
#define SEQ   2048
#define DIM   2048
#define HEADS 16
#define DH    128
#define NEGV  (-10000.0f)
#define MROWS (BATCH * SEQ)          // 4096
#define PLANE ((size_t)MROWS * DIM)  // 8M elems
#define WPLN  ((size_t)DIM * DIM)    // 4M elems

// Scratch (device globals = sanctioned scratch; no allocations allowed)
__device__ __nv_bfloat16 g_Ihi[3 * PLANE];   // split q,k,v inputs (slot 0 reused for ctx)
__device__ __nv_bfloat16 g_Ilo[3 * PLANE];
__device__ __nv_bfloat16 g_Wh3[3 * WPLN];    // split Wq,Wk,Wv (slot 0 reused for Wo)
__device__ __nv_bfloat16 g_Wl3[3 * WPLN];
__device__ __nv_bfloat16 g_Qhi[PLANE];
__device__ __nv_bfloat16 g_Qlo[PLANE];
__device__ __nv_bfloat16 g_Khi[PLANE];
__device__ __nv_bfloat16 g_Klo[PLANE];
__device__ __nv_bfloat16 g_Vhi[PLANE];
__device__ __nv_bfloat16 g_Vlo[PLANE];
__device__ float         g_ctx[PLANE];
__device__ int           g_mask_u8;

// ===========================================================================
// Helpers (baseline PTX only — NO tcgen05/TMEM: harness assembles for sm_103
// without the 'a' suffix; sm_80-era features only)
// ===========================================================================
__device__ __forceinline__ uint32_t smem_u32(const void* p) {
    uint32_t a;
    asm("{ .reg .u64 t; cvta.to.shared.u64 t, %1; cvt.u32.u64 %0, t; }"
        : "=r"(a) : "l"(p));
    return a;
}

__device__ __forceinline__ void ldmx4(uint32_t* r, uint32_t addr) {
    asm volatile("ldmatrix.sync.aligned.m8n8.x4.shared.b16 {%0,%1,%2,%3}, [%4];"
                 : "=r"(r[0]), "=r"(r[1]), "=r"(r[2]), "=r"(r[3]) : "r"(addr));
}

__device__ __forceinline__ void ldmx4t(uint32_t* r, uint32_t addr) {
    asm volatile("ldmatrix.sync.aligned.m8n8.x4.trans.shared.b16 {%0,%1,%2,%3}, [%4];"
                 : "=r"(r[0]), "=r"(r[1]), "=r"(r[2]), "=r"(r[3]) : "r"(addr));
}

__device__ __forceinline__ void mma_bf16(float* c, const uint32_t* a,
                                         const uint32_t* b) {
    asm volatile(
        "mma.sync.aligned.m16n8k16.row.col.f32.bf16.bf16.f32 "
        "{%0,%1,%2,%3}, {%4,%5,%6,%7}, {%8,%9}, {%0,%1,%2,%3};"
        : "+f"(c[0]), "+f"(c[1]), "+f"(c[2]), "+f"(c[3])
        : "r"(a[0]), "r"(a[1]), "r"(a[2]), "r"(a[3]), "r"(b[0]), "r"(b[1]));
}

__device__ __forceinline__ void split_pack(float x0, float x1,
                                           uint32_t& hi, uint32_t& lo) {
    __nv_bfloat16 h0 = __float2bfloat16(x0);
    __nv_bfloat16 h1 = __float2bfloat16(x1);
    __nv_bfloat16 l0 = __float2bfloat16(x0 - __bfloat162float(h0));
    __nv_bfloat16 l1 = __float2bfloat16(x1 - __bfloat162float(h1));
    hi = (uint32_t)__bfloat16_as_ushort(h0) | ((uint32_t)__bfloat16_as_ushort(h1) << 16);
    lo = (uint32_t)__bfloat16_as_ushort(l0) | ((uint32_t)__bfloat16_as_ushort(l1) << 16);
}

__device__ __forceinline__ void cpasync16(uint32_t saddr, const void* g) {
    asm volatile("cp.async.cg.shared.global [%0], [%1], 16;"
                 :: "r"(saddr), "l"(g));
}
#define CP_COMMIT() asm volatile("cp.async.commit_group;" ::: "memory")
#define CP_WAIT1()  asm volatile("cp.async.wait_group 1;" ::: "memory")
#define CP_WAIT0()  asm volatile("cp.async.wait_group 0;" ::: "memory")

// ===========================================================================
// Mask dtype detection (uint8 vs int32 storage of jnp.bool_)
// ===========================================================================
__global__ void detect_mask_kernel(const unsigned int* __restrict__ m)
{
    __shared__ int flag;
    if (threadIdx.x == 0) flag = 0;
    __syncthreads();
    int local = 0;
    for (int i = threadIdx.x; i < 16384; i += blockDim.x)
        if (m[i] > 1u) local = 1;
    if (local) atomicOr(&flag, 1);
    __syncthreads();
    if (threadIdx.x == 0) g_mask_u8 = flag;
}

// ===========================================================================
// Batched fp32 -> split bf16 planes. grid.y selects job; oversized blocks
// (jobs with fewer groups) return early.
// ===========================================================================
struct SplitJobs {
    const float* X[6];
    __nv_bfloat16* Hi[6];
    __nv_bfloat16* Lo[6];
    int n4[6];
};

__global__ void split_many(SplitJobs S)
{
    const int j = blockIdx.y;
    const int i = blockIdx.x * blockDim.x + threadIdx.x;
    if (i >= S.n4[j]) return;
    float4 v = ((const float4*)S.X[j])[i];
    uint32_t h01, l01, h23, l23;
    split_pack(v.x, v.y, h01, l01);
    split_pack(v.z, v.w, h23, l23);
    ((uint2*)S.Hi[j])[i] = make_uint2(h01, h23);
    ((uint2*)S.Lo[j])[i] = make_uint2(l01, l23);
}

// ===========================================================================
// Batched split-bf16 mma.sync GEMM, cp.async double-buffered.
// C[M,N] = A[M,K] @ W[N,K]^T per job (blockIdx.z). Tile 128x128x32, 8 warps.
// ===========================================================================
#define PK     40                      // padded row (32 data + 8) bf16
#define PLANEB (128 * PK * 2)          // 10240 B per plane per stage
#define STAGEB (4 * PLANEB)            // 40960 B
#define GSMEM  (2 * STAGEB)            // 81920 B

struct GemmJobs {
    const __nv_bfloat16* Ah[3];
    const __nv_bfloat16* Al[3];
    const __nv_bfloat16* Wh[3];
    const __nv_bfloat16* Wl[3];
    float*         C [3];
    __nv_bfloat16* Ph[3];
    __nv_bfloat16* Pl[3];
    float          os[3];
};

__device__ __forceinline__ void stage_load(
    uint32_t sbase, const __nv_bfloat16* __restrict__ Ahi,
    const __nv_bfloat16* __restrict__ Alo,
    const __nv_bfloat16* __restrict__ Whi,
    const __nv_bfloat16* __restrict__ Wlo,
    int tid, int bm, int bn, int K, int k0)
{
    #pragma unroll
    for (int it = 0; it < 2; it++) {
        int ch  = tid + it * 256;       // 512 chunks: 128 rows x 4 segs
        int r   = ch >> 2;
        int seg = ch & 3;
        uint32_t so = (uint32_t)(r * (PK * 2) + seg * 16);
        size_t goA = (size_t)(bm + r) * K + k0 + seg * 8;
        size_t goW = (size_t)(bn + r) * K + k0 + seg * 8;
        cpasync16(sbase + 0 * PLANEB + so, Ahi + goA);
        cpasync16(sbase + 1 * PLANEB + so, Alo + goA);
        cpasync16(sbase + 2 * PLANEB + so, Whi + goW);
        cpasync16(sbase + 3 * PLANEB + so, Wlo + goW);
    }
}

__global__ void __launch_bounds__(256, 2)
gemm_bf16(GemmJobs J, int M, int N, int K)
{
    extern __shared__ char smem[];
    const uint32_t sb = smem_u32(smem);

    const int z = blockIdx.z;
    const __nv_bfloat16* __restrict__ Ahi = J.Ah[z];
    const __nv_bfloat16* __restrict__ Alo = J.Al[z];
    const __nv_bfloat16* __restrict__ Whi = J.Wh[z];
    const __nv_bfloat16* __restrict__ Wlo = J.Wl[z];
    float*         C   = J.C[z];
    __nv_bfloat16* Phi = J.Ph[z];
    __nv_bfloat16* Plo = J.Pl[z];
    const float oscale = J.os[z];

    const int tid  = threadIdx.x;
    const int lane = tid & 31;
    const int wid  = tid >> 5;
    const int wm   = wid >> 2;
    const int wn   = wid & 3;
    const int bm   = blockIdx.y * 128;
    const int bn   = blockIdx.x * 128;

    float acc[16][4];
    #pragma unroll
    for (int i = 0; i < 16; i++)
        #pragma unroll
        for (int j = 0; j < 4; j++) acc[i][j] = 0.f;

    const uint32_t offA =
        (uint32_t)(((wm * 64 + (lane & 15)) * PK + ((lane >> 4) << 3)) * 2);
    const uint32_t offB =
        (uint32_t)(((wn * 32 + (((lane >> 3) >> 1) << 3) + (lane & 7)) * PK
                    + (((lane >> 3) & 1) << 3)) * 2);

    const int nch = K >> 5;
    stage_load(sb, Ahi, Alo, Whi, Wlo, tid, bm, bn, K, 0);
    CP_COMMIT();

    for (int ck = 0; ck < nch; ck++) {
        if (ck + 1 < nch) {
            stage_load(sb + ((ck + 1) & 1) * STAGEB, Ahi, Alo, Whi, Wlo,
                       tid, bm, bn, K, (ck + 1) << 5);
            CP_COMMIT();
            CP_WAIT1();
        } else {
            CP_WAIT0();
        }
        __syncthreads();

        const uint32_t st = sb + (ck & 1) * STAGEB;
        const uint32_t bAhi = st, bAlo = st + PLANEB;
        const uint32_t bWhi = st + 2 * PLANEB, bWlo = st + 3 * PLANEB;

        #pragma unroll
        for (int ks = 0; ks < 2; ks++) {
            const uint32_t kb = (uint32_t)(ks * 32);
            uint32_t bh[8], bl[8];
            #pragma unroll
            for (int ntp = 0; ntp < 2; ntp++) {
                uint32_t ro = (uint32_t)(ntp * 16 * PK * 2);
                ldmx4(&bh[ntp * 4], bWhi + offB + ro + kb);
                ldmx4(&bl[ntp * 4], bWlo + offB + ro + kb);
            }
            #pragma unroll
            for (int mt = 0; mt < 4; mt++) {
                uint32_t ah[4], al[4];
                uint32_t ro = (uint32_t)(mt * 16 * PK * 2);
                ldmx4(ah, bAhi + offA + ro + kb);
                ldmx4(al, bAlo + offA + ro + kb);
                #pragma unroll
                for (int nt = 0; nt < 4; nt++) {
                    float* c = acc[mt * 4 + nt];
                    mma_bf16(c, ah, &bh[nt * 2]);
                    mma_bf16(c, ah, &bl[nt * 2]);
                    mma_bf16(c, al, &bh[nt * 2]);
                }
            }
        }
        __syncthreads();
    }

    const int g = lane >> 2;
    const int t = lane & 3;
    #pragma unroll
    for (int mt = 0; mt < 4; mt++) {
        #pragma unroll
        for (int nt = 0; nt < 4; nt++) {
            const float* c = acc[mt * 4 + nt];
            int row = bm + wm * 64 + mt * 16 + g;
            int col = bn + wn * 32 + nt * 8 + 2 * t;
            if (C) {
                *(float2*)(C + (size_t)row * N + col)       = make_float2(c[0], c[1]);
                *(float2*)(C + (size_t)(row + 8) * N + col) = make_float2(c[2], c[3]);
            }
            if (Phi) {
                uint32_t hh, ll;
                split_pack(c[0] * oscale, c[1] * oscale, hh, ll);
                *(uint32_t*)(Phi + (size_t)row * N + col) = hh;
                *(uint32_t*)(Plo + (size_t)row * N + col) = ll;
                split_pack(c[2] * oscale, c[3] * oscale, hh, ll);
                *(uint32_t*)(Phi + (size_t)(row + 8) * N + col) = hh;
                *(uint32_t*)(Plo + (size_t)(row + 8) * N + col) = ll;
            }
        }
    }
}

// ===========================================================================
// Flash attention, split-bf16 mma.sync, pre-split Q/K/V planes.
// BQ=64, BKV=64, 128 threads (4 warps), 2 CTAs/SM -> decoupled softmax/MMA.
// Warp w owns q rows [w*16, w*16+16).
// ===========================================================================
#define PKQ 136   // padded row (128 dh bf16 + 8)
#define PMK 72    // mask tile padded row (64 + 8)

struct FlashSmem2 {
    __nv_bfloat16 Qhi[64 * PKQ];
    __nv_bfloat16 Qlo[64 * PKQ];
    __nv_bfloat16 Khi[64 * PKQ];
    __nv_bfloat16 Klo[64 * PKQ];
    __nv_bfloat16 Vhi[64 * PKQ];
    __nv_bfloat16 Vlo[64 * PKQ];
    unsigned char Msk[64 * PMK];
};   // 109056 bytes -> 2 CTAs/SM

__global__ void __launch_bounds__(128, 2)
flash_mma(const __nv_bfloat16* __restrict__ Qhi, const __nv_bfloat16* __restrict__ Qlo,
          const __nv_bfloat16* __restrict__ Khi, const __nv_bfloat16* __restrict__ Klo,
          const __nv_bfloat16* __restrict__ Vhi, const __nv_bfloat16* __restrict__ Vlo,
          const void* __restrict__ mask_raw, float* __restrict__ ctx)
{
    extern __shared__ char smraw[];
    FlashSmem2* sm = reinterpret_cast<FlashSmem2*>(smraw);

    const int tid  = threadIdx.x;
    const int lane = tid & 31;
    const int w    = tid >> 5;           // 0..3
    const int q0   = blockIdx.x * 64;
    const int bh   = blockIdx.y;
    const int b    = bh >> 4;
    const int h    = bh & 15;
    const int mu8  = g_mask_u8;

    // ---- copy pre-split Q tile (64 x 128 bf16, 2 planes) ----
    const __nv_bfloat16* qh_ = Qhi + ((size_t)b * SEQ + q0) * DIM + h * DH;
    const __nv_bfloat16* ql_ = Qlo + ((size_t)b * SEQ + q0) * DIM + h * DH;
    #pragma unroll
    for (int it = 0; it < 8; it++) {
        int li = tid + it * 128;          // 1024 = 64 rows x 16 uint4
        int r  = li >> 4, c = li & 15;
        uint32_t so = (uint32_t)(r * (PKQ * 2) + c * 16);
        *(uint4*)((char*)sm->Qhi + so) = *(const uint4*)(qh_ + (size_t)r * DIM + c * 8);
        *(uint4*)((char*)sm->Qlo + so) = *(const uint4*)(ql_ + (size_t)r * DIM + c * 8);
    }

    const uint32_t bQhi = smem_u32(sm->Qhi), bQlo = smem_u32(sm->Qlo);
    const uint32_t bKhi = smem_u32(sm->Khi), bKlo = smem_u32(sm->Klo);
    const uint32_t bVhi = smem_u32(sm->Vhi), bVlo = smem_u32(sm->Vlo);

    const uint32_t offA =
        (uint32_t)(((w * 16 + (lane & 15)) * PKQ + ((lane >> 4) << 3)) * 2);
    const uint32_t offB =
        (uint32_t)(((((lane >> 4) & 1) * 8 + (lane & 7)) * PKQ
                    + (((lane >> 3) & 1) << 3)) * 2);
    const uint32_t offV =
        (uint32_t)((((lane & 7) + (((lane >> 3) & 1) << 3)) * PKQ
                    + (((lane >> 4) & 1) << 3)) * 2);

    float Oa[16][4];
    #pragma unroll
    for (int i = 0; i < 16; i++)
        #pragma unroll
        for (int j = 0; j < 4; j++) Oa[i][j] = 0.f;

    float m_g = -1e30f, m_g8 = -1e30f, l_g = 0.f, l_g8 = 0.f;
    const int g = lane >> 2, t = lane & 3;
    const int rg = w * 16 + g, rg8 = rg + 8;

    for (int k0 = 0; k0 < SEQ; k0 += 64) {
        __syncthreads();   // smem reuse guard (also covers initial Q stores)

        // ---- copy pre-split K/V tiles (64 x 128, 4 planes) ----
        const __nv_bfloat16* kh_ = Khi + ((size_t)b * SEQ + k0) * DIM + h * DH;
        const __nv_bfloat16* kl_ = Klo + ((size_t)b * SEQ + k0) * DIM + h * DH;
        const __nv_bfloat16* vh_ = Vhi + ((size_t)b * SEQ + k0) * DIM + h * DH;
        const __nv_bfloat16* vl_ = Vlo + ((size_t)b * SEQ + k0) * DIM + h * DH;
        #pragma unroll
        for (int it = 0; it < 8; it++) {
            int li = tid + it * 128;      // 1024 = 64 rows x 16 uint4
            int r  = li >> 4, c = li & 15;
            uint32_t so = (uint32_t)(r * (PKQ * 2) + c * 16);
            size_t go = (size_t)r * DIM + c * 8;
            *(uint4*)((char*)sm->Khi + so) = *(const uint4*)(kh_ + go);
            *(uint4*)((char*)sm->Klo + so) = *(const uint4*)(kl_ + go);
            *(uint4*)((char*)sm->Vhi + so) = *(const uint4*)(vh_ + go);
            *(uint4*)((char*)sm->Vlo + so) = *(const uint4*)(vl_ + go);
        }

        // ---- stage mask tile (64 q x 64 k) as u8 ----
        if (mu8) {
            const unsigned char* mb = (const unsigned char*)mask_raw
                + (size_t)b * SEQ * SEQ + (size_t)q0 * SEQ + k0;
            #pragma unroll
            for (int it = 0; it < 8; it++) {
                int li = tid + it * 128;
                int r  = li >> 4, c4 = li & 15;
                *(uint32_t*)(sm->Msk + r * PMK + c4 * 4) =
                    *(const uint32_t*)(mb + (size_t)r * SEQ + c4 * 4);
            }
        } else {
            const int* mb = (const int*)mask_raw
                + (size_t)b * SEQ * SEQ + (size_t)q0 * SEQ + k0;
            #pragma unroll
            for (int it = 0; it < 8; it++) {
                int li = tid + it * 128;
                int r  = li >> 4, c4 = li & 15;
                int4 mv = *(const int4*)(mb + (size_t)r * SEQ + c4 * 4);
                uint32_t pk = (mv.x ? 1u : 0u) | ((mv.y ? 1u : 0u) << 8)
                            | ((mv.z ? 1u : 0u) << 16) | ((mv.w ? 1u : 0u) << 24);
                *(uint32_t*)(sm->Msk + r * PMK + c4 * 4) = pk;
            }
        }
        __syncthreads();

        // ---- S = Q . K^T  (split bf16, 3 combos) ----
        float sacc[8][4];
        #pragma unroll
        for (int i = 0; i < 8; i++)
            #pragma unroll
            for (int j = 0; j < 4; j++) sacc[i][j] = 0.f;

        #pragma unroll
        for (int ks = 0; ks < 8; ks++) {
            const uint32_t kb = (uint32_t)(ks * 32);
            uint32_t qh2[4], ql2[4];
            ldmx4(qh2, bQhi + offA + kb);
            ldmx4(ql2, bQlo + offA + kb);
            #pragma unroll
            for (int ntp = 0; ntp < 4; ntp++) {
                const uint32_t ro = (uint32_t)(ntp * 16 * PKQ * 2);
                uint32_t bh2[4], bl2[4];
                ldmx4(bh2, bKhi + offB + ro + kb);
                ldmx4(bl2, bKlo + offB + ro + kb);
                #pragma unroll
                for (int hf = 0; hf < 2; hf++) {
                    float* c = sacc[2 * ntp + hf];
                    mma_bf16(c, qh2, &bh2[hf * 2]);
                    mma_bf16(c, qh2, &bl2[hf * 2]);
                    mma_bf16(c, ql2, &bh2[hf * 2]);
                }
            }
        }

        // ---- mask + online softmax (intra-quad reductions) ----
        float mg = -1e30f, mg8 = -1e30f;
        #pragma unroll
        for (int nt = 0; nt < 8; nt++) {
            float* c = sacc[nt];
            int colb = nt * 8 + 2 * t;
            uchar2 ma  = *(const uchar2*)(sm->Msk + rg  * PMK + colb);
            uchar2 mb2 = *(const uchar2*)(sm->Msk + rg8 * PMK + colb);
            c[0] += ma.x  ? NEGV : 0.f;
            c[1] += ma.y  ? NEGV : 0.f;
            c[2] += mb2.x ? NEGV : 0.f;
            c[3] += mb2.y ? NEGV : 0.f;
            mg  = fmaxf(mg,  fmaxf(c[0], c[1]));
            mg8 = fmaxf(mg8, fmaxf(c[2], c[3]));
        }
        mg  = fmaxf(mg,  __shfl_xor_sync(0xffffffffu, mg, 1));
        mg  = fmaxf(mg,  __shfl_xor_sync(0xffffffffu, mg, 2));
        mg8 = fmaxf(mg8, __shfl_xor_sync(0xffffffffu, mg8, 1));
        mg8 = fmaxf(mg8, __shfl_xor_sync(0xffffffffu, mg8, 2));

        float mn  = fmaxf(m_g,  mg);
        float mn8 = fmaxf(m_g8, mg8);
        float ag  = __expf(m_g  - mn);
        float ag8 = __expf(m_g8 - mn8);
        m_g = mn; m_g8 = mn8;

        float sg = 0.f, sg8 = 0.f;
        #pragma unroll
        for (int nt = 0; nt < 8; nt++) {
            float* c = sacc[nt];
            c[0] = __expf(c[0] - mn);
            c[1] = __expf(c[1] - mn);
            c[2] = __expf(c[2] - mn8);
            c[3] = __expf(c[3] - mn8);
            sg  += c[0] + c[1];
            sg8 += c[2] + c[3];
        }
        sg  += __shfl_xor_sync(0xffffffffu, sg, 1);
        sg  += __shfl_xor_sync(0xffffffffu, sg, 2);
        sg8 += __shfl_xor_sync(0xffffffffu, sg8, 1);
        sg8 += __shfl_xor_sync(0xffffffffu, sg8, 2);
        l_g  = l_g  * ag  + sg;
        l_g8 = l_g8 * ag8 + sg8;

        #pragma unroll
        for (int nt = 0; nt < 16; nt++) {
            Oa[nt][0] *= ag;  Oa[nt][1] *= ag;
            Oa[nt][2] *= ag8; Oa[nt][3] *= ag8;
        }

        // ---- O += P . V  (P split in-register, V split in smem) ----
        #pragma unroll
        for (int ks = 0; ks < 4; ks++) {
            uint32_t ph_[4], pl_[4];
            split_pack(sacc[2*ks][0],   sacc[2*ks][1],   ph_[0], pl_[0]);
            split_pack(sacc[2*ks][2],   sacc[2*ks][3],   ph_[1], pl_[1]);
            split_pack(sacc[2*ks+1][0], sacc[2*ks+1][1], ph_[2], pl_[2]);
            split_pack(sacc[2*ks+1][2], sacc[2*ks+1][3], ph_[3], pl_[3]);
            const uint32_t kro = (uint32_t)(ks * 16 * PKQ * 2);
            #pragma unroll
            for (int ntp = 0; ntp < 8; ntp++) {
                const uint32_t no = (uint32_t)(ntp * 16 * 2);
                uint32_t vh2[4], vl2[4];
                ldmx4t(vh2, bVhi + offV + kro + no);
                ldmx4t(vl2, bVlo + offV + kro + no);
                #pragma unroll
                for (int hf = 0; hf < 2; hf++) {
                    float* o = Oa[2 * ntp + hf];
                    mma_bf16(o, ph_, &vh2[hf * 2]);
                    mma_bf16(o, ph_, &vl2[hf * 2]);
                    mma_bf16(o, pl_, &vh2[hf * 2]);
                }
            }
        }
    }

    // ---- finalize: O / l, write ctx[b, q, h*DH + col] ----
    const float ig  = 1.f / l_g;
    const float ig8 = 1.f / l_g8;
    float* ob = ctx + ((size_t)b * SEQ + q0) * DIM + h * DH;
    #pragma unroll
    for (int nt = 0; nt < 16; nt++) {
        int col = nt * 8 + 2 * t;
        *(float2*)(ob + (size_t)rg  * DIM + col) =
            make_float2(Oa[nt][0] * ig,  Oa[nt][1] * ig);
        *(float2*)(ob + (size_t)rg8 * DIM + col) =
            make_float2(Oa[nt][2] * ig8, Oa[nt][3] * ig8);
    }
}

// ===========================================================================
// Launch
// ===========================================================================
extern "C" void kernel_launch(void* const* d_in, const int* in_sizes, int n_in,
                              void* d_out, int out_size)
{
    const float* q    = (const float*)d_in[0];
    const float* k    = (const float*)d_in[1];
    const float* v    = (const float*)d_in[2];
    const void*  mask = d_in[3];
    const float* Wq   = (const float*)d_in[4];
    const float* Wk   = (const float*)d_in[5];
    const float* Wv   = (const float*)d_in[6];
    const float* Wo   = (const float*)d_in[7];

    float* out = (float*)d_out;
    float* kp = out + PLANE;
    float* vp = out + 2 * PLANE;

    __nv_bfloat16 *Ihi, *Ilo, *Wh3, *Wl3, *Qhi, *Qlo, *Khi, *Klo, *Vhi, *Vlo;
    float* ctx;
    cudaGetSymbolAddress((void**)&Ihi, g_Ihi);
    cudaGetSymbolAddress((void**)&Ilo, g_Ilo);
    cudaGetSymbolAddress((void**)&Wh3, g_Wh3);
    cudaGetSymbolAddress((void**)&Wl3, g_Wl3);
    cudaGetSymbolAddress((void**)&Qhi, g_Qhi);
    cudaGetSymbolAddress((void**)&Qlo, g_Qlo);
    cudaGetSymbolAddress((void**)&Khi, g_Khi);
    cudaGetSymbolAddress((void**)&Klo, g_Klo);
    cudaGetSymbolAddress((void**)&Vhi, g_Vhi);
    cudaGetSymbolAddress((void**)&Vlo, g_Vlo);
    cudaGetSymbolAddress((void**)&ctx, g_ctx);

    const int nA4 = (int)(PLANE / 4);                 // 2M groups
    const int nW4 = (int)(WPLN / 4);                  // 1M groups
    const float qscale = 0.08838834764831843f;        // 1/sqrt(128)

    detect_mask_kernel<<<1, 256>>>((const unsigned int*)mask);

    cudaFuncSetAttribute(gemm_bf16, cudaFuncAttributeMaxDynamicSharedMemorySize,
                         GSMEM);
    cudaFuncSetAttribute(flash_mma, cudaFuncAttributeMaxDynamicSharedMemorySize,
                         (int)sizeof(FlashSmem2));

    // ---- Stage 1: split q,k,v inputs + Wq,Wk,Wv (one batched launch) ----
    {
        SplitJobs S;
        S.X[0] = q;  S.Hi[0] = Ihi;             S.Lo[0] = Ilo;             S.n4[0] = nA4;
        S.X[1] = k;  S.Hi[1] = Ihi + PLANE;     S.Lo[1] = Ilo + PLANE;     S.n4[1] = nA4;
        S.X[2] = v;  S.Hi[2] = Ihi + 2 * PLANE; S.Lo[2] = Ilo + 2 * PLANE; S.n4[2] = nA4;
        S.X[3] = Wq; S.Hi[3] = Wh3;             S.Lo[3] = Wl3;             S.n4[3] = nW4;
        S.X[4] = Wk; S.Hi[4] = Wh3 + WPLN;      S.Lo[4] = Wl3 + WPLN;      S.n4[4] = nW4;
        S.X[5] = Wv; S.Hi[5] = Wh3 + 2 * WPLN;  S.Lo[5] = Wl3 + 2 * WPLN;  S.n4[5] = nW4;
        split_many<<<dim3(nA4 / 256, 6), 256>>>(S);
    }

    // ---- Stage 2: batched Q/K/V projections (one launch, grid.z = 3) ----
    {
        GemmJobs J;
        for (int z = 0; z < 3; z++) {
            J.Ah[z] = Ihi + (size_t)z * PLANE;
            J.Al[z] = Ilo + (size_t)z * PLANE;
            J.Wh[z] = Wh3 + (size_t)z * WPLN;
            J.Wl[z] = Wl3 + (size_t)z * WPLN;
        }
        J.C[0] = nullptr; J.Ph[0] = Qhi; J.Pl[0] = Qlo; J.os[0] = qscale;
        J.C[1] = kp;      J.Ph[1] = Khi; J.Pl[1] = Klo; J.os[1] = 1.0f;
        J.C[2] = vp;      J.Ph[2] = Vhi; J.Pl[2] = Vlo; J.os[2] = 1.0f;
        gemm_bf16<<<dim3(DIM / 128, MROWS / 128, 3), 256, GSMEM>>>(
            J, MROWS, DIM, DIM);
    }

    // ---- Stage 3: flash attention (BQ=64, occ 2) ----
    flash_mma<<<dim3(SEQ / 64, BATCH * HEADS), 128, sizeof(FlashSmem2)>>>(
        Qhi, Qlo, Khi, Klo, Vhi, Vlo, mask, ctx);

    // ---- Stage 4: split ctx + Wo (one batched launch, reuse slot 0) ----
    {
        SplitJobs S;
        S.X[0] = ctx; S.Hi[0] = Ihi; S.Lo[0] = Ilo; S.n4[0] = nA4;
        S.X[1] = Wo;  S.Hi[1] = Wh3; S.Lo[1] = Wl3; S.n4[1] = nW4;
        S.X[2] = ctx; S.Hi[2] = Ihi; S.Lo[2] = Ilo; S.n4[2] = 0;
        S.X[3] = ctx; S.Hi[3] = Ihi; S.Lo[3] = Ilo; S.n4[3] = 0;
        S.X[4] = ctx; S.Hi[4] = Ihi; S.Lo[4] = Ilo; S.n4[4] = 0;
        S.X[5] = ctx; S.Hi[5] = Ihi; S.Lo[5] = Ilo; S.n4[5] = 0;
        split_many<<<dim3(nA4 / 256, 2), 256>>>(S);
    }

    // ---- Stage 5: output projection ----
    {
        GemmJobs J;
        for (int z = 0; z < 3; z++) {
            J.Ah[z] = Ihi; J.Al[z] = Ilo; J.Wh[z] = Wh3; J.Wl[z] = Wl3;
            J.C[z] = out;  J.Ph[z] = nullptr; J.Pl[z] = nullptr; J.os[z] = 1.0f;
        }
        gemm_bf16<<<dim3(DIM / 128, MROWS / 128, 1), 256, GSMEM>>>(
            J, MROWS, DIM, DIM);
    }
}